// round 7
// baseline (speedup 1.0000x reference)
#include <cuda_runtime.h>
#include <cstdint>

#define NB 32
#define LQ 18
#define LK 4096
#define DD 768
#define SCALE_F 0.03608439182435161f   // 1/sqrt(768)

// ---- p1 config ----
#define T1   256
#define MT   128             // k-rows per CTA
#define NMT  (LK/MT)         // 32 m-tiles per batch
#define CC   32              // K cols per chunk
#define NCH  (DD/CC)         // 24 chunks
#define QSTR 1544            // Q row stride bytes (768*2 + 8 pad)
#define KSTR 72              // K tile row stride bytes (32*2 + 8 pad)
#define KBUF 9216            // one K tile buffer (128*72)

// smem layout (bytes)
#define SM_U8   0
#define SM_RED  64           // 8 warps * 24 floats
#define SM_QHI  1024         // 27792
#define SM_QLO  28816
#define SM_KHI  56640        // 2 buffers: +0, +KBUF
#define SM_KLO  (SM_KHI + 2*KBUF)   // 75072, 2 buffers
#define SMEM1_BYTES (SM_KLO + 2*KBUF + 64)  // 93568

// ---- p2 config (at HBM roofline, unchanged) ----
#define TK2 256
#define NT2 (LK/TK2)
#define T2  192

// ---- device scratch ----
__device__ float g_e[(size_t)NB*LQ*LK];
__device__ float g_lp[NB][NMT][LQ];
__device__ float g_cp[NB][NT2][DD];
__device__ int   g_cnt[NB];

__device__ __forceinline__ uint32_t bfpack(float a, float b) {   // low16=bf16(a)
    uint32_t r;
    asm("cvt.rn.bf16x2.f32 %0, %1, %2;" : "=r"(r) : "f"(b), "f"(a));
    return r;
}
__device__ __forceinline__ float bflo_f(uint32_t h) { return __uint_as_float(h << 16); }
__device__ __forceinline__ float bfhi_f(uint32_t h) { return __uint_as_float(h & 0xffff0000u); }

#define MMA(ac, a0,a1,a2,a3, b0,b1) \
    asm volatile("mma.sync.aligned.m16n8k16.row.col.f32.bf16.bf16.f32 " \
        "{%0,%1,%2,%3}, {%4,%5,%6,%7}, {%8,%9}, {%0,%1,%2,%3};" \
        : "+f"((ac)[0]),"+f"((ac)[1]),"+f"((ac)[2]),"+f"((ac)[3]) \
        : "r"(a0),"r"(a1),"r"(a2),"r"(a3),"r"(b0),"r"(b1))

// ---------------- p1: scores^T = K_tile * Q^T via split-bf16 mma.sync ----------------
__global__ __launch_bounds__(T1, 2) void p1(const float* __restrict__ Q,
                                            const float* __restrict__ K,
                                            const void* __restrict__ Mv) {
    extern __shared__ char smem[];
    const int tid = threadIdx.x, w = tid >> 5, lane = tid & 31;
    const int gid = lane >> 2, tig = lane & 3;
    const int b = blockIdx.y, mt = blockIdx.x, k0 = mt * MT;

    if (tid == 0) *(int*)(smem + SM_U8) = 0;
    __syncthreads();
    // mask dtype probe: int32 0/1 has zero bytes at offsets %4!=0; u8 bool does not
    if (tid < 64) {
        uchar4 v = ((const uchar4*)Mv)[tid];
        if (v.y | v.z | v.w) atomicOr((int*)(smem + SM_U8), 1);
    }

    // K row pointer: 2 threads per row, each owns 16 floats (4 float4) per 32-col chunk
    const int krow = tid >> 1, khalf = tid & 1;
    const float4* KP = (const float4*)(K + ((size_t)b * LK + k0 + krow) * DD);

    // prefetch chunk 0
    float4 kr[4], kn[4];
#pragma unroll
    for (int f = 0; f < 4; f++) kr[f] = KP[khalf * 4 + f];

    // Q -> bf16 hi/lo smem (one time)
    {
        const float4* Q4 = (const float4*)(Q + (size_t)b * LQ * DD);
        for (int idx = tid; idx < LQ * 192; idx += T1) {
            int q = idx / 192, f = idx % 192;
            float4 v = Q4[idx];
            uint32_t h0 = bfpack(v.x, v.y), h1 = bfpack(v.z, v.w);
            uint32_t l0 = bfpack(v.x - bflo_f(h0), v.y - bfhi_f(h0));
            uint32_t l1 = bfpack(v.z - bflo_f(h1), v.w - bfhi_f(h1));
            *(uint2*)(smem + SM_QHI + q * QSTR + f * 8) = make_uint2(h0, h1);
            *(uint2*)(smem + SM_QLO + q * QSTR + f * 8) = make_uint2(l0, l1);
        }
    }

    float acc[3][4];
#pragma unroll
    for (int nt = 0; nt < 3; nt++)
#pragma unroll
        for (int i = 0; i < 4; i++) acc[nt][i] = 0.f;

    const int M0 = w * 16;
    const uint32_t cvt_off = (uint32_t)(krow * KSTR + khalf * 32);

    for (int c = 0; c < NCH; c++) {
        // register-prefetch chunk c+1
        if (c + 1 < NCH) {
#pragma unroll
            for (int f = 0; f < 4; f++) kn[f] = KP[(c + 1) * 8 + khalf * 4 + f];
        }
        // convert chunk c (in kr) -> bf16 hi/lo buffer c&1
        {
            const uint32_t base = (uint32_t)((c & 1) * KBUF);
#pragma unroll
            for (int f = 0; f < 4; f++) {
                uint32_t h0 = bfpack(kr[f].x, kr[f].y), h1 = bfpack(kr[f].z, kr[f].w);
                uint32_t l0 = bfpack(kr[f].x - bflo_f(h0), kr[f].y - bfhi_f(h0));
                uint32_t l1 = bfpack(kr[f].z - bflo_f(h1), kr[f].w - bfhi_f(h1));
                uint32_t o = base + cvt_off + f * 8;
                *(uint2*)(smem + SM_KHI + o) = make_uint2(h0, h1);
                *(uint2*)(smem + SM_KLO + o) = make_uint2(l0, l1);
            }
        }
        __syncthreads();   // buffer c&1 ready; also guarantees MMA(c-1) done before convert(c+1)

        // MMA chunk c from buffer c&1
        {
            const int base = (c & 1) * KBUF;
#pragma unroll
            for (int s = 0; s < 2; s++) {
                const int kc = s * 16;
                const char* ka = smem + SM_KHI + base + (M0 + gid) * KSTR + (kc + tig * 2) * 2;
                const char* la = smem + SM_KLO + base + (M0 + gid) * KSTR + (kc + tig * 2) * 2;
                uint32_t ah0 = *(const uint32_t*)ka;
                uint32_t ah1 = *(const uint32_t*)(ka + 8 * KSTR);
                uint32_t ah2 = *(const uint32_t*)(ka + 16);
                uint32_t ah3 = *(const uint32_t*)(ka + 8 * KSTR + 16);
                uint32_t al0 = *(const uint32_t*)la;
                uint32_t al1 = *(const uint32_t*)(la + 8 * KSTR);
                uint32_t al2 = *(const uint32_t*)(la + 16);
                uint32_t al3 = *(const uint32_t*)(la + 8 * KSTR + 16);
                const int dglob = c * CC + kc + tig * 2;
#pragma unroll
                for (int nt = 0; nt < 3; nt++) {
                    int q = nt * 8 + gid; if (q > 17) q = 17;   // clamp pad rows
                    const char* qh = smem + SM_QHI + q * QSTR + dglob * 2;
                    const char* ql = smem + SM_QLO + q * QSTR + dglob * 2;
                    uint32_t bh0 = *(const uint32_t*)qh;
                    uint32_t bh1 = *(const uint32_t*)(qh + 16);
                    uint32_t bl0 = *(const uint32_t*)ql;
                    uint32_t bl1 = *(const uint32_t*)(ql + 16);
                    MMA(acc[nt], ah0, ah1, ah2, ah3, bh0, bh1);
                    MMA(acc[nt], ah0, ah1, ah2, ah3, bl0, bl1);
                    MMA(acc[nt], al0, al1, al2, al3, bh0, bh1);
                }
            }
        }
#pragma unroll
        for (int f = 0; f < 4; f++) kr[f] = kn[f];
    }

    // epilogue: mask + exp + g_e store + per-q row sums
    const int u8 = *(volatile int*)(smem + SM_U8);
    const unsigned char* M8  = (const unsigned char*)Mv;
    const int*           M32 = (const int*)Mv;
    float* red = (float*)(smem + SM_RED);
    const int ra = M0 + gid, rb = ra + 8;
#pragma unroll
    for (int nt = 0; nt < 3; nt++) {
        const int q0 = nt * 8 + tig * 2, q1 = q0 + 1;
        float e0 = 0.f, e1 = 0.f, e2 = 0.f, e3 = 0.f;
        if (q0 < LQ) {
            size_t o = ((size_t)b * LQ + q0) * LK + k0;
            int m0 = u8 ? (int)M8[o + ra] : M32[o + ra];
            int m2 = u8 ? (int)M8[o + rb] : M32[o + rb];
            e0 = m0 ? 0.f : __expf(acc[nt][0] * SCALE_F);
            e2 = m2 ? 0.f : __expf(acc[nt][2] * SCALE_F);
            g_e[o + ra] = e0;
            g_e[o + rb] = e2;
        }
        if (q1 < LQ) {
            size_t o = ((size_t)b * LQ + q1) * LK + k0;
            int m1 = u8 ? (int)M8[o + ra] : M32[o + ra];
            int m3 = u8 ? (int)M8[o + rb] : M32[o + rb];
            e1 = m1 ? 0.f : __expf(acc[nt][1] * SCALE_F);
            e3 = m3 ? 0.f : __expf(acc[nt][3] * SCALE_F);
            g_e[o + ra] = e1;
            g_e[o + rb] = e3;
        }
        float s0 = e0 + e2, s1 = e1 + e3;
#pragma unroll
        for (int m = 4; m <= 16; m <<= 1) {
            s0 += __shfl_xor_sync(0xffffffffu, s0, m);
            s1 += __shfl_xor_sync(0xffffffffu, s1, m);
        }
        if (gid == 0) {
            if (q0 < LQ) red[w * 24 + q0] = s0;
            if (q1 < LQ) red[w * 24 + q1] = s1;
        }
    }
    __syncthreads();
    if (tid < LQ) {
        float l = 0.f;
#pragma unroll
        for (int ww = 0; ww < 8; ww++) l += red[ww * 24 + tid];
        g_lp[b][mt][tid] = l;
    }
}

// ---------------- p2: attn_fc + context (unchanged; at HBM roofline) ----------------
__global__ __launch_bounds__(T2) void p2(const float* __restrict__ V,
                                         const float* __restrict__ W,
                                         float* __restrict__ out) {
    __shared__ float wl[LQ];
    __shared__ float sa[TK2];
    __shared__ int s_last;
    const int tid  = threadIdx.x;
    const int b    = blockIdx.y;
    const int tile = blockIdx.x;
    const int k0   = tile * TK2;

    if (tid < LQ) {
        float l = 0.f;
#pragma unroll
        for (int t = 0; t < NMT; t++) l += g_lp[b][t][tid];
        wl[tid] = W[tid] / l;
    }
    __syncthreads();

    for (int kk = tid; kk < TK2; kk += T2) {
        const int k = k0 + kk;
        float a = 0.f;
#pragma unroll
        for (int q = 0; q < LQ; q++)
            a = fmaf(g_e[((size_t)b*LQ + q)*LK + k], wl[q], a);
        out[(size_t)NB*DD + (size_t)b*LK + k] = a;
        sa[kk] = a;
    }
    __syncthreads();

    const float4* V4 = (const float4*)(V + ((size_t)b*LK + k0)*DD);
    float cx = 0.f, cy = 0.f, cz = 0.f, cw = 0.f;
#pragma unroll 8
    for (int kk = 0; kk < TK2; kk++) {
        float  av = sa[kk];
        float4 v  = V4[(size_t)kk*(DD/4) + tid];
        cx = fmaf(av, v.x, cx);
        cy = fmaf(av, v.y, cy);
        cz = fmaf(av, v.z, cz);
        cw = fmaf(av, v.w, cw);
    }
    ((float4*)g_cp[b][tile])[tid] = make_float4(cx, cy, cz, cw);
    __threadfence();
    __syncthreads();
    if (tid == 0) s_last = (atomicAdd(&g_cnt[b], 1) == NT2 - 1);
    __syncthreads();
    if (s_last) {
        float4 a = make_float4(0.f, 0.f, 0.f, 0.f);
#pragma unroll
        for (int t = 0; t < NT2; t++) {
            float4 v = ((const float4*)g_cp[b][t])[tid];
            a.x += v.x; a.y += v.y; a.z += v.z; a.w += v.w;
        }
        ((float4*)(out + (size_t)b*DD))[tid] = a;
        if (tid == 0) g_cnt[b] = 0;
    }
}

extern "C" void kernel_launch(void* const* d_in, const int* in_sizes, int n_in,
                              void* d_out, int out_size) {
    const float* Q = (const float*)d_in[0];
    const float* K = (const float*)d_in[1];
    const float* V = (const float*)d_in[2];
    const void*  M = d_in[3];
    const float* W = (const float*)d_in[4];
    float* out = (float*)d_out;

    cudaFuncSetAttribute(p1, cudaFuncAttributeMaxDynamicSharedMemorySize, SMEM1_BYTES);

    p1<<<dim3(NMT, NB), T1, SMEM1_BYTES>>>(Q, K, M);
    p2<<<dim3(NT2, NB), T2>>>(V, W, out);
}